// round 1
// baseline (speedup 1.0000x reference)
#include <cuda_runtime.h>
#include <cstdint>

// Problem constants
#define Bc   8
#define Tc   256
#define Uc   64
#define Dc   640
#define Vc   1024
#define K2c  1280
#define ME   (Bc*Tc)        // 2048 rows of E
#define MP   (Bc*Uc)        // 512 rows of P
#define MOUT (Bc*Tc*Uc)     // 131072 output rows

// Scratch (device globals — no allocation allowed)
__device__ __align__(16) float g_E[ME * Vc];   // 8 MB
__device__ __align__(16) float g_P[MP * Vc];   // 2 MB

__device__ __forceinline__ uint32_t f2tf(float x) {
    uint32_t r;
    asm("cvt.rna.tf32.f32 %0, %1;" : "=r"(r) : "f"(x));
    return r;
}

// ---------------------------------------------------------------------------
// C[M,N] = ReLU(A[M,K]) @ W[:, kOff:kOff+K]^T  (+ bias)
// A row-major lda=Dc, W row-major ldw=K2c. BM=BN=128, BK=32, 256 thr, tf32 mma.
// outSel: 0 -> g_E, 1 -> g_P
// ---------------------------------------------------------------------------
__global__ __launch_bounds__(256) void gemm_relu_tf32(
    const float* __restrict__ A,
    const float* __restrict__ W,
    int kOff,
    const float* __restrict__ bias,   // nullptr for E
    int outSel)
{
    __shared__ uint32_t As[128][36];  // [m][k], pad 4
    __shared__ uint32_t Bs[128][36];  // [n][k], pad 4

    float* __restrict__ C = outSel ? g_P : g_E;

    const int tid  = threadIdx.x;
    const int bm0  = blockIdx.y * 128;
    const int bn0  = blockIdx.x * 128;
    const int warp = tid >> 5;
    const int lane = tid & 31;
    const int g    = lane >> 2;       // 0..7
    const int q    = lane & 3;        // 0..3
    const int mBase = (warp & 3) * 32;   // 4 warps along M
    const int nBase = (warp >> 2) * 64;  // 2 warps along N

    float c[2][8][4];
#pragma unroll
    for (int mt = 0; mt < 2; mt++)
#pragma unroll
        for (int nt = 0; nt < 8; nt++)
#pragma unroll
            for (int r = 0; r < 4; r++) c[mt][nt][r] = 0.f;

    const int lr = tid >> 3;        // 0..31  (row within 32-row slab)
    const int lc = (tid & 7) * 4;   // 0,4,...,28

    for (int k0 = 0; k0 < Dc; k0 += 32) {
        // stage tiles
#pragma unroll
        for (int i = 0; i < 4; i++) {
            int row = lr + i * 32;
            float4 a = *(const float4*)&A[(size_t)(bm0 + row) * Dc + k0 + lc];
            As[row][lc + 0] = f2tf(fmaxf(a.x, 0.f));
            As[row][lc + 1] = f2tf(fmaxf(a.y, 0.f));
            As[row][lc + 2] = f2tf(fmaxf(a.z, 0.f));
            As[row][lc + 3] = f2tf(fmaxf(a.w, 0.f));
            float4 w = *(const float4*)&W[(size_t)(bn0 + row) * K2c + kOff + k0 + lc];
            Bs[row][lc + 0] = f2tf(w.x);
            Bs[row][lc + 1] = f2tf(w.y);
            Bs[row][lc + 2] = f2tf(w.z);
            Bs[row][lc + 3] = f2tf(w.w);
        }
        __syncthreads();

#pragma unroll
        for (int kk = 0; kk < 4; kk++) {
            uint32_t af[2][4];
#pragma unroll
            for (int mt = 0; mt < 2; mt++) {
                int r0 = mBase + mt * 16;
                af[mt][0] = As[r0 + g    ][kk * 8 + q    ];
                af[mt][1] = As[r0 + g + 8][kk * 8 + q    ];
                af[mt][2] = As[r0 + g    ][kk * 8 + q + 4];
                af[mt][3] = As[r0 + g + 8][kk * 8 + q + 4];
            }
            uint32_t bf[8][2];
#pragma unroll
            for (int nt = 0; nt < 8; nt++) {
                int n = nBase + nt * 8 + g;
                bf[nt][0] = Bs[n][kk * 8 + q    ];
                bf[nt][1] = Bs[n][kk * 8 + q + 4];
            }
#pragma unroll
            for (int mt = 0; mt < 2; mt++)
#pragma unroll
                for (int nt = 0; nt < 8; nt++) {
                    asm volatile(
                        "mma.sync.aligned.m16n8k8.row.col.f32.tf32.tf32.f32 "
                        "{%0,%1,%2,%3}, {%4,%5,%6,%7}, {%8,%9}, {%0,%1,%2,%3};\n"
                        : "+f"(c[mt][nt][0]), "+f"(c[mt][nt][1]),
                          "+f"(c[mt][nt][2]), "+f"(c[mt][nt][3])
                        : "r"(af[mt][0]), "r"(af[mt][1]), "r"(af[mt][2]), "r"(af[mt][3]),
                          "r"(bf[nt][0]), "r"(bf[nt][1]));
                }
        }
        __syncthreads();
    }

    // epilogue
#pragma unroll
    for (int mt = 0; mt < 2; mt++) {
        int row = bm0 + mBase + mt * 16 + g;
#pragma unroll
        for (int nt = 0; nt < 8; nt++) {
            int col = bn0 + nBase + nt * 8 + q * 2;
            float b0 = 0.f, b1 = 0.f;
            if (bias) { b0 = bias[col]; b1 = bias[col + 1]; }
            C[(size_t)row * Vc + col]           = c[mt][nt][0] + b0;
            C[(size_t)row * Vc + col + 1]       = c[mt][nt][1] + b1;
            C[(size_t)(row + 8) * Vc + col]     = c[mt][nt][2] + b0;
            C[(size_t)(row + 8) * Vc + col + 1] = c[mt][nt][3] + b1;
        }
    }
}

// ---------------------------------------------------------------------------
// out[((b*T+t)*U+u)*V + v] = E[(b*T+t)*V + v] + P[(b*U+u)*V + v]
// float4 vectorized; E rows are reused 64x consecutively -> L2 resident.
// ---------------------------------------------------------------------------
__global__ __launch_bounds__(256) void expand_kernel(float4* __restrict__ out)
{
    const float4* __restrict__ E4 = (const float4*)g_E;
    const float4* __restrict__ P4 = (const float4*)g_P;
    int idx = blockIdx.x * 256 + threadIdx.x;     // 0 .. 33554431
    int v4  = idx & 255;                          // V/4 = 256
    int row = idx >> 8;                           // output row
    int u   = row & 63;
    int bt  = row >> 6;                           // b*T + t
    int b   = bt >> 8;                            // T = 256
    float4 e = E4[bt * 256 + v4];
    float4 p = P4[(b * 64 + u) * 256 + v4];
    float4 r;
    r.x = e.x + p.x; r.y = e.y + p.y; r.z = e.z + p.z; r.w = e.w + p.w;
    out[idx] = r;
}

// Passthrough lengths appended as floats (tuple outputs concatenated).
__global__ void tail_kernel(float* __restrict__ out,
                            const int* __restrict__ slen,
                            const int* __restrict__ tlen)
{
    int i = threadIdx.x;
    size_t base = (size_t)MOUT * Vc;
    if (i < 8)       out[base + i]     = (float)slen[i];
    else if (i < 16) out[base + i]     = (float)tlen[i - 8];
}

extern "C" void kernel_launch(void* const* d_in, const int* in_sizes, int n_in,
                              void* d_out, int out_size)
{
    const float* enc  = (const float*)d_in[0];  // [B,T,D]
    const int*   slen = (const int*)  d_in[1];  // [B]
    const float* pred = (const float*)d_in[2];  // [B,U,D]
    const int*   tlen = (const int*)  d_in[3];  // [B]
    const float* W    = (const float*)d_in[4];  // [V, 2D]
    const float* bias = (const float*)d_in[5];  // [V]
    float* out = (float*)d_out;

    // P = ReLU(pred) @ Wp^T + bias   (512 x 1024)
    gemm_relu_tf32<<<dim3(Vc / 128, MP / 128), 256>>>(pred, W, Dc, bias, 1);
    // E = ReLU(enc) @ We^T           (2048 x 1024)
    gemm_relu_tf32<<<dim3(Vc / 128, ME / 128), 256>>>(enc, W, 0, nullptr, 0);

    // out = broadcast add over the (T,U) lattice: 131072 x 1024 fp32
    expand_kernel<<<(MOUT * (Vc / 4)) / 256, 256>>>((float4*)out);

    // appended passthrough outputs, if the harness buffer includes them
    if (out_size >= (int)((size_t)MOUT * Vc + 16)) {
        tail_kernel<<<1, 16>>>(out, slen, tlen);
    }
}

// round 2
// speedup vs baseline: 1.7283x; 1.7283x over previous
#include <cuda_runtime.h>
#include <cstdint>

// Problem constants
#define Bc   8
#define Tc   256
#define Uc   64
#define Dc   640
#define Vc   1024
#define K2c  1280
#define ME   (Bc*Tc)        // 2048 rows of E
#define MP   (Bc*Uc)        // 512 rows of P
#define MOUT (Bc*Tc*Uc)     // 131072 output rows

// Scratch (device globals — no allocation allowed)
__device__ __align__(16) float g_E[ME * Vc];   // 8 MB
__device__ __align__(16) float g_P[MP * Vc];   // 2 MB

__device__ __forceinline__ uint32_t f2tf(float x) {
    uint32_t r;
    asm("cvt.rna.tf32.f32 %0, %1;" : "=r"(r) : "f"(x));
    return r;
}

// ---------------------------------------------------------------------------
// Fused dual GEMM:  blockIdx.y < 16 : g_E = ReLU(enc) @ W[:, :640]^T
//                   blockIdx.y >= 16: g_P = ReLU(pred) @ W[:, 640:]^T + bias
// BM=BN=128, BK=32, 256 threads, tf32 mma, register prefetch of next K tile.
// ---------------------------------------------------------------------------
__global__ __launch_bounds__(256) void gemm_dual_tf32(
    const float* __restrict__ enc,
    const float* __restrict__ pred,
    const float* __restrict__ W,
    const float* __restrict__ bias)
{
    __shared__ uint32_t As[128][36];  // [m][k], pad 4
    __shared__ uint32_t Bs[128][36];  // [n][k], pad 4

    const int by = blockIdx.y;
    const float* __restrict__ A;
    float* __restrict__ C;
    int kOff, bm0;
    const float* bptr;
    if (by < 16) { A = enc;  C = g_E; kOff = 0;  bm0 = by * 128;        bptr = nullptr; }
    else         { A = pred; C = g_P; kOff = Dc; bm0 = (by - 16) * 128; bptr = bias;    }

    const int tid  = threadIdx.x;
    const int bn0  = blockIdx.x * 128;
    const int warp = tid >> 5;
    const int lane = tid & 31;
    const int g    = lane >> 2;       // 0..7
    const int q    = lane & 3;        // 0..3
    const int mBase = (warp & 3) * 32;   // 4 warps along M
    const int nBase = (warp >> 2) * 64;  // 2 warps along N

    float c[2][8][4];
#pragma unroll
    for (int mt = 0; mt < 2; mt++)
#pragma unroll
        for (int nt = 0; nt < 8; nt++)
#pragma unroll
            for (int r = 0; r < 4; r++) c[mt][nt][r] = 0.f;

    const int lr = tid >> 3;        // 0..31  (row within 32-row slab)
    const int lc = (tid & 7) * 4;   // 0,4,...,28

    // prologue: prefetch k0 = 0 into registers
    float4 ra[4], rw[4];
#pragma unroll
    for (int i = 0; i < 4; i++) {
        int row = lr + i * 32;
        ra[i] = *(const float4*)&A[(size_t)(bm0 + row) * Dc + lc];
        rw[i] = *(const float4*)&W[(size_t)(bn0 + row) * K2c + kOff + lc];
    }

    for (int k0 = 0; k0 < Dc; k0 += 32) {
        // commit registers to smem (with ReLU + tf32 round)
#pragma unroll
        for (int i = 0; i < 4; i++) {
            int row = lr + i * 32;
            As[row][lc + 0] = f2tf(fmaxf(ra[i].x, 0.f));
            As[row][lc + 1] = f2tf(fmaxf(ra[i].y, 0.f));
            As[row][lc + 2] = f2tf(fmaxf(ra[i].z, 0.f));
            As[row][lc + 3] = f2tf(fmaxf(ra[i].w, 0.f));
            Bs[row][lc + 0] = f2tf(rw[i].x);
            Bs[row][lc + 1] = f2tf(rw[i].y);
            Bs[row][lc + 2] = f2tf(rw[i].z);
            Bs[row][lc + 3] = f2tf(rw[i].w);
        }
        __syncthreads();

        // prefetch next K tile while the mma pipeline drains from smem
        if (k0 + 32 < Dc) {
#pragma unroll
            for (int i = 0; i < 4; i++) {
                int row = lr + i * 32;
                ra[i] = *(const float4*)&A[(size_t)(bm0 + row) * Dc + k0 + 32 + lc];
                rw[i] = *(const float4*)&W[(size_t)(bn0 + row) * K2c + kOff + k0 + 32 + lc];
            }
        }

#pragma unroll
        for (int kk = 0; kk < 4; kk++) {
            uint32_t af[2][4];
#pragma unroll
            for (int mt = 0; mt < 2; mt++) {
                int r0 = mBase + mt * 16;
                af[mt][0] = As[r0 + g    ][kk * 8 + q    ];
                af[mt][1] = As[r0 + g + 8][kk * 8 + q    ];
                af[mt][2] = As[r0 + g    ][kk * 8 + q + 4];
                af[mt][3] = As[r0 + g + 8][kk * 8 + q + 4];
            }
            uint32_t bf[8][2];
#pragma unroll
            for (int nt = 0; nt < 8; nt++) {
                int n = nBase + nt * 8 + g;
                bf[nt][0] = Bs[n][kk * 8 + q    ];
                bf[nt][1] = Bs[n][kk * 8 + q + 4];
            }
#pragma unroll
            for (int mt = 0; mt < 2; mt++)
#pragma unroll
                for (int nt = 0; nt < 8; nt++) {
                    asm volatile(
                        "mma.sync.aligned.m16n8k8.row.col.f32.tf32.tf32.f32 "
                        "{%0,%1,%2,%3}, {%4,%5,%6,%7}, {%8,%9}, {%0,%1,%2,%3};\n"
                        : "+f"(c[mt][nt][0]), "+f"(c[mt][nt][1]),
                          "+f"(c[mt][nt][2]), "+f"(c[mt][nt][3])
                        : "r"(af[mt][0]), "r"(af[mt][1]), "r"(af[mt][2]), "r"(af[mt][3]),
                          "r"(bf[nt][0]), "r"(bf[nt][1]));
                }
        }
        __syncthreads();
    }

    // epilogue
#pragma unroll
    for (int mt = 0; mt < 2; mt++) {
        int row = bm0 + mBase + mt * 16 + g;
#pragma unroll
        for (int nt = 0; nt < 8; nt++) {
            int col = bn0 + nBase + nt * 8 + q * 2;
            float b0 = 0.f, b1 = 0.f;
            if (bptr) { b0 = bptr[col]; b1 = bptr[col + 1]; }
            C[(size_t)row * Vc + col]           = c[mt][nt][0] + b0;
            C[(size_t)row * Vc + col + 1]       = c[mt][nt][1] + b1;
            C[(size_t)(row + 8) * Vc + col]     = c[mt][nt][2] + b0;
            C[(size_t)(row + 8) * Vc + col + 1] = c[mt][nt][3] + b1;
        }
    }
}

// ---------------------------------------------------------------------------
// Tiled expand: block = (32 t) x (64 u) x (128 v) tile of the output.
//   grid = (V/128=8, T/32=8, B=8), 256 threads.
// Stage E tile (32x128 f32 = 16KB) + P tile (64x128 f32 = 32KB) in shared;
// each output element costs 1 LDS.128 + 1 STG.128. Global reads ~25MB total.
// Block (0,0,0) also writes the two passthrough length vectors.
// ---------------------------------------------------------------------------
__global__ __launch_bounds__(256) void expand_tiled(
    float4* __restrict__ out,
    const int* __restrict__ slen,
    const int* __restrict__ tlen,
    int writeTail)
{
    __shared__ float4 sE[32][32];   // [t][vq]  16KB
    __shared__ float4 sP[64][32];   // [u][vq]  32KB

    const float4* __restrict__ E4 = (const float4*)g_E;
    const float4* __restrict__ P4 = (const float4*)g_P;

    const int tid = threadIdx.x;
    const int v0q = blockIdx.x * 32;   // float4 column offset within a row
    const int t0  = blockIdx.y * 32;
    const int b   = blockIdx.z;

    // load E tile: 32 rows x 32 float4 = 1024 float4, 4 per thread
#pragma unroll
    for (int i = 0; i < 4; i++) {
        int idx = tid + i * 256;
        int r = idx >> 5, cq = idx & 31;
        sE[r][cq] = E4[(size_t)(b * Tc + t0 + r) * 256 + v0q + cq];
    }
    // load P tile: 64 rows x 32 float4 = 2048 float4, 8 per thread
#pragma unroll
    for (int i = 0; i < 8; i++) {
        int idx = tid + i * 256;
        int r = idx >> 5, cq = idx & 31;
        sP[r][cq] = P4[(size_t)(b * Uc + r) * 256 + v0q + cq];
    }
    __syncthreads();

    const int vq   = tid & 31;
    const int warp = tid >> 5;     // 0..7, each warp owns 4 t-rows

#pragma unroll
    for (int ti = 0; ti < 4; ti++) {
        int t = warp * 4 + ti;
        float4 e = sE[t][vq];
        // base output index (in float4): row = ((b*T + t0+t)*U + u), rowlen=256
        size_t base = ((size_t)((b * Tc + t0 + t) * Uc)) * 256 + v0q + vq;
#pragma unroll 4
        for (int u = 0; u < Uc; u++) {
            float4 p = sP[u][vq];
            float4 r;
            r.x = e.x + p.x; r.y = e.y + p.y; r.z = e.z + p.z; r.w = e.w + p.w;
            out[base + (size_t)u * 256] = r;
        }
    }

    // passthrough lengths appended after the joint output
    if (writeTail && blockIdx.x == 0 && blockIdx.y == 0 && blockIdx.z == 0 && tid < 16) {
        float* o = (float*)out;
        size_t tb = (size_t)MOUT * Vc;
        if (tid < 8) o[tb + tid] = (float)slen[tid];
        else         o[tb + tid] = (float)tlen[tid - 8];
    }
}

extern "C" void kernel_launch(void* const* d_in, const int* in_sizes, int n_in,
                              void* d_out, int out_size)
{
    const float* enc  = (const float*)d_in[0];  // [B,T,D]
    const int*   slen = (const int*)  d_in[1];  // [B]
    const float* pred = (const float*)d_in[2];  // [B,U,D]
    const int*   tlen = (const int*)  d_in[3];  // [B]
    const float* W    = (const float*)d_in[4];  // [V, 2D]
    const float* bias = (const float*)d_in[5];  // [V]
    float* out = (float*)d_out;

    // E and P GEMMs fused into one launch: grid.y = 16 (E) + 4 (P)
    gemm_dual_tf32<<<dim3(Vc / 128, 20), 256>>>(enc, pred, W, bias);

    int writeTail = (out_size >= (int)((size_t)MOUT * Vc + 16)) ? 1 : 0;
    expand_tiled<<<dim3(Vc / 128, Tc / 32, Bc), 256>>>(
        (float4*)out, slen, tlen, writeTail);
}

// round 3
// speedup vs baseline: 2.8688x; 1.6599x over previous
#include <cuda_runtime.h>
#include <cstdint>

// Problem constants
#define Bc   8
#define Tc   256
#define Uc   64
#define Dc   640
#define Vc   1024
#define K2c  1280
#define MOUT (Bc*Tc*Uc)     // 131072 output rows

__device__ __forceinline__ uint32_t f2tf(float x) {
    uint32_t r;
    asm("cvt.rna.tf32.f32 %0, %1;" : "=r"(r) : "f"(x));
    return r;
}

// Shared memory union: GEMM staging vs expand tiles (max 49152 B = 48KB static)
struct __align__(16) SmemU {
    union {
        struct { uint32_t As[128][36]; uint32_t Bs[128][36]; } g;  // 36928 B
        struct { float E[32][128]; float P[64][128]; } x;          // 49152 B
    };
};

// ---------------------------------------------------------------------------
// ONE fused kernel. grid = (V/128 = 8, 2*B = 16), 256 threads.
//   Block (bx, by): b = by>>1, thalf = (by&1)*128, v-cols [bx*128, bx*128+128)
// Phase A: E-tile[128 t x 128 v] = ReLU(enc rows) @ We^T      (regs cE)
// Phase B: P-tile[ 64 u x 128 v] = ReLU(pred rows) @ Wp^T + b (regs cP)
// Phase C: expand — stage P in smem, stage E in 32-row slabs, write
//          out[b, t, u, v] = E[t][v] + P[u][v]  (4 MB per block)
// ---------------------------------------------------------------------------
__global__ __launch_bounds__(256, 1) void fused_joiner(
    const float* __restrict__ enc,
    const float* __restrict__ pred,
    const float* __restrict__ W,
    const float* __restrict__ bias,
    float4* __restrict__ out,
    const int* __restrict__ slen,
    const int* __restrict__ tlen,
    int writeTail)
{
    __shared__ SmemU sm;

    const int tid  = threadIdx.x;
    const int warp = tid >> 5;
    const int lane = tid & 31;
    const int g    = lane >> 2;     // 0..7
    const int q    = lane & 3;      // 0..3
    const int bn0  = blockIdx.x * 128;            // v-col offset
    const int b    = blockIdx.y >> 1;
    const int thalf= (blockIdx.y & 1) * 128;
    const int bt0  = b * Tc + thalf;              // first enc row of this block

    const int lr = tid >> 3;        // 0..31
    const int lc = (tid & 7) * 4;   // 0,4..28

    // ===================== Phase A: E tile (128x128) =====================
    const int mA = (warp & 3) * 32;
    const int nA = (warp >> 2) * 64;
    float cE[2][8][4];
#pragma unroll
    for (int mt = 0; mt < 2; mt++)
#pragma unroll
        for (int nt = 0; nt < 8; nt++)
#pragma unroll
            for (int r = 0; r < 4; r++) cE[mt][nt][r] = 0.f;

    float4 ra[4], rw[4];
#pragma unroll
    for (int i = 0; i < 4; i++) {
        ra[i] = *(const float4*)&enc[(size_t)(bt0 + lr + i * 32) * Dc + lc];
        rw[i] = *(const float4*)&W[(size_t)(bn0 + lr + i * 32) * K2c + lc];
    }

    for (int k0 = 0; k0 < Dc; k0 += 32) {
#pragma unroll
        for (int i = 0; i < 4; i++) {
            int row = lr + i * 32;
            sm.g.As[row][lc+0] = f2tf(fmaxf(ra[i].x, 0.f));
            sm.g.As[row][lc+1] = f2tf(fmaxf(ra[i].y, 0.f));
            sm.g.As[row][lc+2] = f2tf(fmaxf(ra[i].z, 0.f));
            sm.g.As[row][lc+3] = f2tf(fmaxf(ra[i].w, 0.f));
            sm.g.Bs[row][lc+0] = f2tf(rw[i].x);
            sm.g.Bs[row][lc+1] = f2tf(rw[i].y);
            sm.g.Bs[row][lc+2] = f2tf(rw[i].z);
            sm.g.Bs[row][lc+3] = f2tf(rw[i].w);
        }
        __syncthreads();
        if (k0 + 32 < Dc) {
#pragma unroll
            for (int i = 0; i < 4; i++) {
                ra[i] = *(const float4*)&enc[(size_t)(bt0 + lr + i * 32) * Dc + k0 + 32 + lc];
                rw[i] = *(const float4*)&W[(size_t)(bn0 + lr + i * 32) * K2c + k0 + 32 + lc];
            }
        }
#pragma unroll
        for (int kk = 0; kk < 4; kk++) {
            uint32_t af[2][4];
#pragma unroll
            for (int mt = 0; mt < 2; mt++) {
                int r0 = mA + mt * 16;
                af[mt][0] = sm.g.As[r0 + g    ][kk*8 + q    ];
                af[mt][1] = sm.g.As[r0 + g + 8][kk*8 + q    ];
                af[mt][2] = sm.g.As[r0 + g    ][kk*8 + q + 4];
                af[mt][3] = sm.g.As[r0 + g + 8][kk*8 + q + 4];
            }
#pragma unroll
            for (int nt = 0; nt < 8; nt++) {
                int n = nA + nt * 8 + g;
                uint32_t b0 = sm.g.Bs[n][kk*8 + q];
                uint32_t b1 = sm.g.Bs[n][kk*8 + q + 4];
                asm volatile(
                    "mma.sync.aligned.m16n8k8.row.col.f32.tf32.tf32.f32 "
                    "{%0,%1,%2,%3}, {%4,%5,%6,%7}, {%8,%9}, {%0,%1,%2,%3};\n"
                    : "+f"(cE[0][nt][0]), "+f"(cE[0][nt][1]),
                      "+f"(cE[0][nt][2]), "+f"(cE[0][nt][3])
                    : "r"(af[0][0]), "r"(af[0][1]), "r"(af[0][2]), "r"(af[0][3]),
                      "r"(b0), "r"(b1));
                asm volatile(
                    "mma.sync.aligned.m16n8k8.row.col.f32.tf32.tf32.f32 "
                    "{%0,%1,%2,%3}, {%4,%5,%6,%7}, {%8,%9}, {%0,%1,%2,%3};\n"
                    : "+f"(cE[1][nt][0]), "+f"(cE[1][nt][1]),
                      "+f"(cE[1][nt][2]), "+f"(cE[1][nt][3])
                    : "r"(af[1][0]), "r"(af[1][1]), "r"(af[1][2]), "r"(af[1][3]),
                      "r"(b0), "r"(b1));
            }
        }
        __syncthreads();
    }

    // ===================== Phase B: P tile (64x128) =====================
    const int mB = (warp & 1) * 32;
    const int nB = (warp >> 1) * 32;
    float cP[2][4][4];
#pragma unroll
    for (int mt = 0; mt < 2; mt++)
#pragma unroll
        for (int nt = 0; nt < 4; nt++)
#pragma unroll
            for (int r = 0; r < 4; r++) cP[mt][nt][r] = 0.f;

#pragma unroll
    for (int i = 0; i < 2; i++)
        ra[i] = *(const float4*)&pred[(size_t)(b * Uc + lr + i * 32) * Dc + lc];
#pragma unroll
    for (int i = 0; i < 4; i++)
        rw[i] = *(const float4*)&W[(size_t)(bn0 + lr + i * 32) * K2c + Dc + lc];

    for (int k0 = 0; k0 < Dc; k0 += 32) {
#pragma unroll
        for (int i = 0; i < 2; i++) {
            int row = lr + i * 32;
            sm.g.As[row][lc+0] = f2tf(fmaxf(ra[i].x, 0.f));
            sm.g.As[row][lc+1] = f2tf(fmaxf(ra[i].y, 0.f));
            sm.g.As[row][lc+2] = f2tf(fmaxf(ra[i].z, 0.f));
            sm.g.As[row][lc+3] = f2tf(fmaxf(ra[i].w, 0.f));
        }
#pragma unroll
        for (int i = 0; i < 4; i++) {
            int row = lr + i * 32;
            sm.g.Bs[row][lc+0] = f2tf(rw[i].x);
            sm.g.Bs[row][lc+1] = f2tf(rw[i].y);
            sm.g.Bs[row][lc+2] = f2tf(rw[i].z);
            sm.g.Bs[row][lc+3] = f2tf(rw[i].w);
        }
        __syncthreads();
        if (k0 + 32 < Dc) {
#pragma unroll
            for (int i = 0; i < 2; i++)
                ra[i] = *(const float4*)&pred[(size_t)(b * Uc + lr + i * 32) * Dc + k0 + 32 + lc];
#pragma unroll
            for (int i = 0; i < 4; i++)
                rw[i] = *(const float4*)&W[(size_t)(bn0 + lr + i * 32) * K2c + Dc + k0 + 32 + lc];
        }
#pragma unroll
        for (int kk = 0; kk < 4; kk++) {
            uint32_t af[2][4];
#pragma unroll
            for (int mt = 0; mt < 2; mt++) {
                int r0 = mB + mt * 16;
                af[mt][0] = sm.g.As[r0 + g    ][kk*8 + q    ];
                af[mt][1] = sm.g.As[r0 + g + 8][kk*8 + q    ];
                af[mt][2] = sm.g.As[r0 + g    ][kk*8 + q + 4];
                af[mt][3] = sm.g.As[r0 + g + 8][kk*8 + q + 4];
            }
#pragma unroll
            for (int nt = 0; nt < 4; nt++) {
                int n = nB + nt * 8 + g;
                uint32_t b0 = sm.g.Bs[n][kk*8 + q];
                uint32_t b1 = sm.g.Bs[n][kk*8 + q + 4];
#pragma unroll
                for (int mt = 0; mt < 2; mt++) {
                    asm volatile(
                        "mma.sync.aligned.m16n8k8.row.col.f32.tf32.tf32.f32 "
                        "{%0,%1,%2,%3}, {%4,%5,%6,%7}, {%8,%9}, {%0,%1,%2,%3};\n"
                        : "+f"(cP[mt][nt][0]), "+f"(cP[mt][nt][1]),
                          "+f"(cP[mt][nt][2]), "+f"(cP[mt][nt][3])
                        : "r"(af[mt][0]), "r"(af[mt][1]), "r"(af[mt][2]), "r"(af[mt][3]),
                          "r"(b0), "r"(b1));
                }
            }
        }
        __syncthreads();
    }

    // ===================== Phase C: expand =====================
    // Write P tile (+bias) into smem (overwrites Bs region — gemm done).
#pragma unroll
    for (int mt = 0; mt < 2; mt++) {
        int row = mB + mt * 16 + g;
#pragma unroll
        for (int nt = 0; nt < 4; nt++) {
            int col = nB + nt * 8 + q * 2;
            float b0 = bias[bn0 + col];
            float b1 = bias[bn0 + col + 1];
            sm.x.P[row    ][col    ] = cP[mt][nt][0] + b0;
            sm.x.P[row    ][col + 1] = cP[mt][nt][1] + b1;
            sm.x.P[row + 8][col    ] = cP[mt][nt][2] + b0;
            sm.x.P[row + 8][col + 1] = cP[mt][nt][3] + b1;
        }
    }

    const int vq = lane;  // float4 column 0..31 within the 128-col v-tile
    // Process E in 4 slabs of 32 t-rows (sm.x.E reused per slab).
#pragma unroll 1
    for (int s = 0; s < 4; s++) {
        // warps owning slab s write their accumulators into sm.x.E
        if ((warp & 3) == s) {
#pragma unroll
            for (int mt = 0; mt < 2; mt++) {
                int row = mt * 16 + g;   // local row within slab
#pragma unroll
                for (int nt = 0; nt < 8; nt++) {
                    int col = nA + nt * 8 + q * 2;
                    sm.x.E[row    ][col    ] = cE[mt][nt][0];
                    sm.x.E[row    ][col + 1] = cE[mt][nt][1];
                    sm.x.E[row + 8][col    ] = cE[mt][nt][2];
                    sm.x.E[row + 8][col + 1] = cE[mt][nt][3];
                }
            }
        }
        __syncthreads();

        // expand: warp w handles 4 t-rows, fixed vq; loop u: 1 LDS + 4 STG
        float4 e[4];
        size_t obase[4];
#pragma unroll
        for (int ti = 0; ti < 4; ti++) {
            int tl = warp * 4 + ti;                    // local t row in slab
            e[ti] = ((const float4*)sm.x.E[tl])[vq];
            int trow = bt0 + s * 32 + tl;              // global bt row
            obase[ti] = (size_t)trow * Uc * 256 + blockIdx.x * 32 + vq;
        }
#pragma unroll 4
        for (int u = 0; u < Uc; u++) {
            float4 p = ((const float4*)sm.x.P[u])[vq];
#pragma unroll
            for (int ti = 0; ti < 4; ti++) {
                float4 r;
                r.x = e[ti].x + p.x; r.y = e[ti].y + p.y;
                r.z = e[ti].z + p.z; r.w = e[ti].w + p.w;
                out[obase[ti] + (size_t)u * 256] = r;
            }
        }
        __syncthreads();
    }

    // passthrough lengths appended after the joint output
    if (writeTail && blockIdx.x == 0 && blockIdx.y == 0 && tid < 16) {
        float* o = (float*)out;
        size_t tb = (size_t)MOUT * Vc;
        if (tid < 8) o[tb + tid] = (float)slen[tid];
        else         o[tb + tid] = (float)tlen[tid - 8];
    }
}

extern "C" void kernel_launch(void* const* d_in, const int* in_sizes, int n_in,
                              void* d_out, int out_size)
{
    const float* enc  = (const float*)d_in[0];  // [B,T,D]
    const int*   slen = (const int*)  d_in[1];  // [B]
    const float* pred = (const float*)d_in[2];  // [B,U,D]
    const int*   tlen = (const int*)  d_in[3];  // [B]
    const float* W    = (const float*)d_in[4];  // [V, 2D]
    const float* bias = (const float*)d_in[5];  // [V]
    float* out = (float*)d_out;

    int writeTail = (out_size >= (int)((size_t)MOUT * Vc + 16)) ? 1 : 0;
    fused_joiner<<<dim3(Vc / 128, 2 * Bc), 256>>>(
        enc, pred, W, bias, (float4*)out, slen, tlen, writeTail);
}